// round 3
// baseline (speedup 1.0000x reference)
#include <cuda_runtime.h>
#include <math.h>

// Problem constants: B=32, N=160, C=3, L=128
// SSIM: VALID 11x11 gaussian -> 150x150 output
// STFT: f=12, s=4 -> p=38 patches/dim, bins u,v in 1..5, weight u*v/25

#define SSIM_BLOCKS (5*5*96)   // 25 tiles x (32 b * 3 c) = 2400
#define STFT_BLOCKS (38*32)    // patch rows x batch = 1216

__device__ float g_ssim[SSIM_BLOCKS];
__device__ float g_stft[STFT_BLOCKS];

typedef unsigned long long ull;

// ---- packed f32x2 primitives (sm_100+ PTX; ptxas never emits these itself) ----
#define FMA2(d, a, b, c) asm("fma.rn.f32x2 %0, %1, %2, %3;" : "=l"(d) : "l"(a), "l"(b), "l"(c))
#define MUL2(d, a, b)    asm("mul.rn.f32x2 %0, %1, %2;"     : "=l"(d) : "l"(a), "l"(b))
#define ADD2(d, a, b)    asm("add.rn.f32x2 %0, %1, %2;"     : "=l"(d) : "l"(a), "l"(b))
#define SUB2(d, a, b)    asm("sub.rn.f32x2 %0, %1, %2;"     : "=l"(d) : "l"(a), "l"(b))

__device__ __forceinline__ ull pk(float lo, float hi) {
    ull r; asm("mov.b64 %0, {%1, %2};" : "=l"(r) : "f"(lo), "f"(hi)); return r;
}
__device__ __forceinline__ float2 up2(ull v) {
    float2 r; asm("mov.b64 {%0, %1}, %2;" : "=f"(r.x), "=f"(r.y) : "l"(v)); return r;
}

// gaussian weights (normalized), compile-time immediates, symmetric
__device__ __forceinline__ constexpr float GNW(int k) {
    constexpr float g[11] = {0.00102838f, 0.00759887f, 0.03600077f, 0.10936069f,
                             0.21300553f, 0.26601172f, 0.21300553f, 0.10936069f,
                             0.03600077f, 0.00759887f, 0.00102838f};
    return g[k];
}

// ---------------------------------------------------------------------------
// SSIM kernel: separable gaussian. 32x32 output tile, 256 threads.
// (x,y) packed f32x2 everywhere; moment fields packed ulonglong2 + scalar.
// ---------------------------------------------------------------------------
__global__ void __launch_bounds__(256, 5) ssim_kernel(const float* __restrict__ xin,
                                                      const float* __restrict__ xout)
{
    __shared__ ull        sxy[42][43];   // (x,y) packed        : 14.4KB
    __shared__ ulonglong2 hab[42][33];   // ((hx,hy),(hxx,hyy)) : 22.2KB
    __shared__ float      hc [42][33];   // hxy                 :  5.5KB
    __shared__ float      red[256];

    const int bz = blockIdx.z;           // b*3 + c
    const int c  = bz % 3, b = bz / 3;
    const int ox = blockIdx.x * 32, oy = blockIdx.y * 32;
    const int tid = threadIdx.x;

    // packed gaussian weights (6 distinct, symmetric)
    ull ww[6];
    #pragma unroll
    for (int k = 0; k < 6; k++) ww[k] = pk(GNW(k), GNW(k));

    const float* pin  = xin  + (size_t)b * (160*160*3) + c;
    const float* pout = xout + (size_t)b * (160*160*3) + c;

    // load 42x42 input tile (halo), zero-pad OOB (those outputs masked)
    for (int i = tid; i < 42*42; i += 256) {
        int r = i / 42, cc = i - r*42;
        int gr = oy + r, gc = ox + cc;
        float vx = 0.f, vy = 0.f;
        if (gr < 160 && gc < 160) {
            size_t off = ((size_t)gr*160 + gc) * 3;
            vx = pin[off]; vy = pout[off];
        }
        sxy[r][cc] = pk(vx, vy);
    }
    __syncthreads();

    // horizontal pass: 42 rows x 8 groups of 4 output cols, k-outer.
    for (int i = tid; i < 42*8; i += 256) {
        int r = i >> 3, c0 = (i & 7) * 4;
        ull a01[4] = {0,0,0,0}, a23[4] = {0,0,0,0};
        float a4[4] = {0.f, 0.f, 0.f, 0.f};
        #pragma unroll
        for (int k = 0; k < 14; k++) {
            ull xy = sxy[r][c0 + k];
            float2 xyu = up2(xy);
            #pragma unroll
            for (int g = 0; g < 4; g++) {
                const int kk = k - g;
                if (kk >= 0 && kk < 11) {
                    const int wi = (kk <= 5) ? kk : 10 - kk;
                    ull wxy; MUL2(wxy, ww[wi], xy);
                    ADD2(a01[g], a01[g], wxy);
                    FMA2(a23[g], wxy, xy, a23[g]);
                    a4[g] = fmaf(up2(wxy).x, xyu.y, a4[g]);
                }
            }
        }
        #pragma unroll
        for (int g = 0; g < 4; g++) {
            hab[r][c0 + g] = make_ulonglong2(a01[g], a23[g]);
            hc [r][c0 + g] = a4[g];
        }
    }
    __syncthreads();

    // vertical pass: 32 cols x 8 row-groups, 4 outputs/thread, k-outer.
    const int tx = tid & 31, ty = tid >> 5;
    const int rb = ty * 4;

    ull a01[4] = {0,0,0,0}, a23[4] = {0,0,0,0};
    float a4[4] = {0.f, 0.f, 0.f, 0.f};

    #pragma unroll
    for (int k = 0; k < 14; k++) {
        ulonglong2 t = hab[rb + k][tx];
        float t4 = hc[rb + k][tx];
        #pragma unroll
        for (int g = 0; g < 4; g++) {
            const int kk = k - g;
            if (kk >= 0 && kk < 11) {
                const int wi = (kk <= 5) ? kk : 10 - kk;
                FMA2(a01[g], ww[wi], t.x, a01[g]);
                FMA2(a23[g], ww[wi], t.y, a23[g]);
                a4[g] = fmaf(GNW(kk), t4, a4[g]);
            }
        }
    }

    float val = 0.f;
    const int gx = ox + tx;
    #pragma unroll
    for (int g = 0; g < 4; g++) {
        int gy = oy + rb + g;
        if (gx < 150 && gy < 150) {
            const float C1 = 1e-4f, C2 = 9e-4f;
            float2 m01 = up2(a01[g]);
            float2 e23 = up2(a23[g]);
            float mx = m01.x, my = m01.y;
            float vx  = e23.x - mx*mx;
            float vy  = e23.y - my*my;
            float cov = a4[g] - mx*my;
            float lum = __fdividef(2.f*mx*my + C1, mx*mx + my*my + C1);
            float cs  = __fdividef(2.f*cov + C2, vx + vy + C2);
            val = fmaf(lum, cs, val);
        }
    }

    red[tid] = val;
    __syncthreads();
    #pragma unroll
    for (int s = 128; s > 0; s >>= 1) {
        if (tid < s) red[tid] += red[tid + s];
        __syncthreads();
    }
    if (tid == 0)
        g_ssim[(size_t)bz*25 + blockIdx.y*5 + blockIdx.x] = red[0];
}

// ---------------------------------------------------------------------------
// STFT helpers
// ---------------------------------------------------------------------------
__device__ __forceinline__ constexpr float cw12f(int k) {
    constexpr float t[12] = { 1.f, 0.86602540378f, 0.5f, 0.f, -0.5f, -0.86602540378f,
                             -1.f,-0.86602540378f,-0.5f, 0.f,  0.5f,  0.86602540378f};
    return t[k];
}
__device__ __forceinline__ constexpr float sw12f(int k) {
    constexpr float t[12] = { 0.f, 0.5f, 0.86602540378f, 1.f, 0.86602540378f, 0.5f,
                              0.f,-0.5f,-0.86602540378f,-1.f,-0.86602540378f,-0.5f};
    return t[k];
}

// packed 12-point real-input DFT on (in,out) pairs, bins u=1..5
__device__ __forceinline__ void dft12_5_x2(const ull* __restrict__ v,
                                           ull* __restrict__ hr,
                                           ull* __restrict__ hi,
                                           ull p05, ull m05, ull pS3, ull mS3)
{
    const ull ZERO = 0;
    ull t, a, bb;
    ull A1, B1, D1, A2, B2, D2;
    SUB2(A1, v[1], v[5]);  SUB2(A1, A1, v[7]);  ADD2(A1, A1, v[11]);
    SUB2(B1, v[2], v[4]);  SUB2(B1, B1, v[8]);  ADD2(B1, B1, v[10]);
    SUB2(D1, v[0], v[6]);
    ADD2(A2, v[1], v[5]);  SUB2(A2, A2, v[7]);  SUB2(A2, A2, v[11]);
    ADD2(B2, v[2], v[4]);  SUB2(B2, B2, v[8]);  SUB2(B2, B2, v[10]);
    SUB2(D2, v[3], v[9]);
    ull t1, t2, s1, s2;
    MUL2(t1, pS3, A1); MUL2(t2, p05, B1);
    MUL2(s1, p05, A2); MUL2(s2, pS3, B2);
    // u=1
    ADD2(t, t1, t2); ADD2(hr[0], D1, t);
    ADD2(t, s1, s2); ADD2(t, t, D2); SUB2(hi[0], ZERO, t);
    // u=5
    SUB2(t, t2, t1); ADD2(hr[4], D1, t);
    SUB2(t, s1, s2); ADD2(t, t, D2); SUB2(hi[4], ZERO, t);
    // even bins
    ull p0, p3, q1, q2, q4, q5;
    ADD2(p0, v[0], v[6]); ADD2(p3, v[3], v[9]);
    ADD2(q1, v[1], v[7]); ADD2(q2, v[2], v[8]);
    ADD2(q4, v[4], v[10]); ADD2(q5, v[5], v[11]);
    // u=2: hr = (p0-p3) + 0.5*((q1+q5)-(q2+q4)) ; hi = -S3*((q1+q2)-(q4+q5))
    ADD2(a, q1, q5); ADD2(bb, q2, q4); SUB2(a, a, bb);
    SUB2(t, p0, p3); FMA2(hr[1], p05, a, t);
    ADD2(a, q1, q2); ADD2(bb, q4, q5); SUB2(a, a, bb); MUL2(hi[1], mS3, a);
    // u=3: hr = (v0+v4+v8)-(v2+v6+v10) ; hi = (v3+v7+v11)-(v1+v5+v9)
    ADD2(a, v[0], v[4]); ADD2(a, a, v[8]);
    ADD2(bb, v[2], v[6]); ADD2(bb, bb, v[10]); SUB2(hr[2], a, bb);
    ADD2(a, v[3], v[7]); ADD2(a, a, v[11]);
    ADD2(bb, v[1], v[5]); ADD2(bb, bb, v[9]); SUB2(hi[2], a, bb);
    // u=4: hr = E0 - 0.5*(E1+E2) ; hi = -S3*(E1-E2)
    ull E0, E1, E2;
    ADD2(E0, p0, p3); ADD2(E1, q1, q4); ADD2(E2, q2, q5);
    ADD2(t, E1, E2); FMA2(hr[3], m05, t, E0);
    SUB2(t, E1, E2); MUL2(hi[3], mS3, t);
}

// accumulate F += h * e^{-2*pi*i*k/12} on packed (in,out) pairs.
// k is compile-time after full unroll -> branches fold away.
__device__ __forceinline__ void cmadd(int k, ull& Fr, ull& Fi, ull hre, ull him,
                                      ull p05, ull m05, ull pS3, ull mS3)
{
    if (k == 0)      { ADD2(Fr, Fr, hre); ADD2(Fi, Fi, him); }
    else if (k == 6) { SUB2(Fr, Fr, hre); SUB2(Fi, Fi, him); }
    else if (k == 3) { ADD2(Fr, Fr, him); SUB2(Fi, Fi, hre); }   // tw = -i
    else if (k == 9) { SUB2(Fr, Fr, him); ADD2(Fi, Fi, hre); }   // tw = +i
    else {
        const float c = cw12f(k), s = sw12f(k);
        ull C2  = (c == 0.5f) ? p05 : (c == -0.5f) ? m05 : (c > 0.f) ? pS3 : mS3;
        ull S2  = (s == 0.5f) ? p05 : (s == -0.5f) ? m05 : (s > 0.f) ? pS3 : mS3;
        ull NS2 = (s == 0.5f) ? m05 : (s == -0.5f) ? p05 : (s > 0.f) ? mS3 : pS3;
        FMA2(Fr, hre, C2, Fr); FMA2(Fr, him, S2, Fr);
        FMA2(Fi, him, C2, Fi); FMA2(Fi, hre, NS2, Fi);
    }
}

__device__ __forceinline__ float fast_atan2f(float y, float x) {
    float ax = fabsf(x), ay = fabsf(y);
    float mx = fmaxf(ax, ay), mn = fminf(ax, ay);
    float t = __fdividef(mn, mx);
    float s = t*t;
    float p =             -0.01172120f;
    p = fmaf(p, s,         0.05265332f);
    p = fmaf(p, s,        -0.11643287f);
    p = fmaf(p, s,         0.19354346f);
    p = fmaf(p, s,        -0.33262347f);
    p = fmaf(p, s,         0.99997726f);
    float r = p * t;
    if (ay > ax)  r = 1.57079632679f - r;
    if (x < 0.f)  r = 3.14159265359f - r;
    return copysignf(r, y);
}

// ---------------------------------------------------------------------------
// STFT kernel: block = (patch_row, batch), 192 threads.
// Phase A: packed column DFT (both images at once) per absolute column -> H.
// Phase B: per (patch, channel, u): 12-pt x-DFT, packed (in,out) f32x2 MACs.
// ---------------------------------------------------------------------------
__global__ void __launch_bounds__(192, 5) stft_kernel(const float* __restrict__ xin,
                                                      const float* __restrict__ xout)
{
    __shared__ ulonglong2 H[5][540];      // [u][swizzled col] = {(reI,reO),(imI,imO)}
    __shared__ float red[256];

    const int b = blockIdx.y;
    const int prow = blockIdx.x;          // image rows prow*4 .. prow*4+11
    const int tid = threadIdx.x;

    const float S3 = 0.86602540378f;
    const ull p05 = pk(0.5f, 0.5f), m05 = pk(-0.5f, -0.5f);
    const ull pS3 = pk(S3, S3),     mS3 = pk(-S3, -S3);

    const float* pin  = xin  + ((long)b * 160 + (long)prow * 4) * 480;
    const float* pout = xout + ((long)b * 160 + (long)prow * 4) * 480;

    // ---- Phase A: packed column DFTs straight from gmem ----
    for (int e = tid; e < 480; e += 192) {
        ull v[12];
        #pragma unroll
        for (int y = 0; y < 12; y++)
            v[y] = pk(pin[y*480 + e], pout[y*480 + e]);
        ull hr[5], hi[5];
        dft12_5_x2(v, hr, hi, p05, m05, pS3, mS3);
        const int es = e + (e >> 3);      // bank swizzle
        #pragma unroll
        for (int u = 0; u < 5; u++)
            H[u][es] = make_ulonglong2(hr[u], hi[u]);
    }
    __syncthreads();

    // ---- Phase B: 570 items = 38 patches x 3 ch x 5 u ----
    float acc = 0.f;
    for (int id = tid; id < 570; id += 192) {
        const int u = id / 114;           // 0..4  (bin u+1)
        const int m = id - u*114;         // 0..113 = j*3 + c
        const int cch = m % 3;
        const int ebase = 4*m - 3*cch;    // = 12j + c

        ull Fr[5] = {0,0,0,0,0}, Fi[5] = {0,0,0,0,0};

        #pragma unroll
        for (int x = 0; x < 12; x++) {
            const int e = ebase + 3*x;
            const int es = e + (e >> 3);
            const ulonglong2 h = H[u][es];
            #pragma unroll
            for (int v = 1; v <= 5; v++)
                cmadd((v*x) % 12, Fr[v-1], Fi[v-1], h.x, h.y, p05, m05, pS3, mS3);
        }

        // epilogue: arg + amp differences, weight u*v/25
        const float wu = (float)(u + 1) * (1.f / 25.f);
        #pragma unroll
        for (int v = 1; v <= 5; v++) {
            float2 fr = up2(Fr[v-1]);     // (Fir, For)
            float2 fi = up2(Fi[v-1]);     // (Fii, Foi)
            float angi = fast_atan2f(fi.x, fr.x + 1e-8f);
            float ango = fast_atan2f(fi.y, fr.y + 1e-8f);
            float m2i = fmaf(fr.x, fr.x, fi.x*fi.x);
            float m2o = fmaf(fr.y, fr.y, fi.y*fi.y);
            float magi = m2i * __frsqrt_rn(fmaxf(m2i, 1e-30f));
            float mago = m2o * __frsqrt_rn(fmaxf(m2o, 1e-30f));
            acc = fmaf((float)v * wu, fabsf(ango - angi) + fabsf(mago - magi), acc);
        }
    }

    red[tid] = acc;
    if (tid < 64) red[tid + 192] = 0.f;   // pad to 256
    __syncthreads();
    #pragma unroll
    for (int s = 128; s > 0; s >>= 1) {
        if (tid < s) red[tid] += red[tid + s];
        __syncthreads();
    }
    if (tid == 0)
        g_stft[blockIdx.y*38 + blockIdx.x] = red[0];
}

// ---------------------------------------------------------------------------
// Final kernel: deterministic fixed-order fp64 reduction.
// loss = mean_b( -0.5*sum(1+lv-e^lv-m^2) + ssim_mean + 1e-4*stft_sum )
// ---------------------------------------------------------------------------
__global__ void __launch_bounds__(512) final_kernel(const float* __restrict__ mean,
                                                    const float* __restrict__ logvar,
                                                    float* __restrict__ out)
{
    __shared__ double red[512];
    const int tid = threadIdx.x;
    double acc = 0.0;

    const double K_KLD  = -0.5 / 32.0;
    const double K_SSIM = 1.0 / (32.0 * 150.0 * 150.0 * 3.0);
    const double K_STFT = 1e-4 / 32.0;

    for (int i = tid; i < 32*128; i += 512) {
        float lv = logvar[i], m = mean[i];
        acc += (double)(1.0f + lv - expf(lv) - m*m) * K_KLD;
    }
    for (int i = tid; i < SSIM_BLOCKS; i += 512)
        acc += (double)g_ssim[i] * K_SSIM;
    for (int i = tid; i < STFT_BLOCKS; i += 512)
        acc += (double)g_stft[i] * K_STFT;

    red[tid] = acc;
    __syncthreads();
    #pragma unroll
    for (int s = 256; s > 0; s >>= 1) {
        if (tid < s) red[tid] += red[tid + s];
        __syncthreads();
    }
    if (tid == 0) out[0] = (float)red[0];
}

// ---------------------------------------------------------------------------
extern "C" void kernel_launch(void* const* d_in, const int* in_sizes, int n_in,
                              void* d_out, int out_size)
{
    const float* mean   = (const float*)d_in[0];
    const float* logvar = (const float*)d_in[1];
    const float* xin    = (const float*)d_in[2];
    const float* xout   = (const float*)d_in[3];
    float* out = (float*)d_out;

    ssim_kernel<<<dim3(5, 5, 96), 256>>>(xin, xout);
    stft_kernel<<<dim3(38, 32), 192>>>(xin, xout);
    final_kernel<<<1, 512>>>(mean, logvar, out);
}

// round 4
// speedup vs baseline: 1.7013x; 1.7013x over previous
#include <cuda_runtime.h>
#include <math.h>

// Problem constants: B=32, N=160, C=3, L=128
// SSIM: VALID 11x11 gaussian -> 150x150 output
// STFT: f=12, s=4 -> p=38 patches/dim, bins u,v in 1..5, weight u*v/25

#define SSIM_BLOCKS (5*5*96)   // 25 tiles x (32 b * 3 c) = 2400
#define STFT_BLOCKS (38*32)    // patch rows x batch = 1216
#define TOTAL_BLOCKS (SSIM_BLOCKS + STFT_BLOCKS)

__device__ float g_ssim[SSIM_BLOCKS];
__device__ float g_stft[STFT_BLOCKS];

// gaussian weights (normalized), compile-time immediates
__device__ __forceinline__ constexpr float GNW(int k) {
    constexpr float g[11] = {0.00102838f, 0.00759887f, 0.03600077f, 0.10936069f,
                             0.21300553f, 0.26601172f, 0.21300553f, 0.10936069f,
                             0.03600077f, 0.00759887f, 0.00102838f};
    return g[k];
}

__device__ __forceinline__ constexpr float cw12f(int k) {
    constexpr float t[12] = { 1.f, 0.86602540378f, 0.5f, 0.f, -0.5f, -0.86602540378f,
                             -1.f,-0.86602540378f,-0.5f, 0.f,  0.5f,  0.86602540378f};
    return t[k];
}
__device__ __forceinline__ constexpr float sw12f(int k) {
    constexpr float t[12] = { 0.f, 0.5f, 0.86602540378f, 1.f, 0.86602540378f, 0.5f,
                              0.f,-0.5f,-0.86602540378f,-1.f,-0.86602540378f,-0.5f};
    return t[k];
}

// 12-point real-input DFT, bins u=1..5, hand-factored
__device__ __forceinline__ void dft12_5(const float* __restrict__ v,
                                        float* __restrict__ hr,
                                        float* __restrict__ hi)
{
    const float S3 = 0.86602540378f;
    float A1 = v[1]-v[5]-v[7]+v[11];
    float B1 = v[2]-v[4]-v[8]+v[10];
    float D1 = v[0]-v[6];
    float A2 = v[1]+v[5]-v[7]-v[11];
    float B2 = v[2]+v[4]-v[8]-v[10];
    float D2 = v[3]-v[9];
    float t1 = S3*A1, t2 = 0.5f*B1;
    float s1 = 0.5f*A2, s2 = S3*B2;
    hr[0] = D1 + t1 + t2;            hi[0] = -(s1 + s2 + D2);   // u=1
    hr[4] = D1 - t1 + t2;            hi[4] = -(s1 - s2 + D2);   // u=5
    float p0 = v[0]+v[6], p3 = v[3]+v[9];
    float q1 = v[1]+v[7], q2 = v[2]+v[8], q4 = v[4]+v[10], q5 = v[5]+v[11];
    hr[1] = (p0 - p3) + 0.5f*((q1+q5) - (q2+q4));               // u=2
    hi[1] = -S3*((q1+q2) - (q4+q5));
    hr[2] = (v[0]+v[4]+v[8]) - (v[2]+v[6]+v[10]);               // u=3
    hi[2] = (v[3]+v[7]+v[11]) - (v[1]+v[5]+v[9]);
    float E0 = p0+p3, E1 = q1+q4, E2 = q2+q5;
    hr[3] = E0 - 0.5f*(E1+E2);                                  // u=4
    hi[3] = -S3*(E1-E2);
}

__device__ __forceinline__ float fast_atan2f(float y, float x) {
    float ax = fabsf(x), ay = fabsf(y);
    float mx = fmaxf(ax, ay), mn = fminf(ax, ay);
    float t = __fdividef(mn, mx);
    float s = t*t;
    float p =             -0.01172120f;
    p = fmaf(p, s,         0.05265332f);
    p = fmaf(p, s,        -0.11643287f);
    p = fmaf(p, s,         0.19354346f);
    p = fmaf(p, s,        -0.33262347f);
    p = fmaf(p, s,         0.99997726f);
    float r = p * t;
    if (ay > ax)  r = 1.57079632679f - r;
    if (x < 0.f)  r = 3.14159265359f - r;
    return copysignf(r, y);
}

// ---------------------------------------------------------------------------
// Fused compute kernel: bid < STFT_BLOCKS -> stft work; else ssim work.
// 256 threads. Shared memory is a union of the two working sets (+ aliased
// reduction buffer; guarded by __syncthreads before first write).
// ---------------------------------------------------------------------------
union SmemU {
    float red[256];                       // aliases the fronts (sync-guarded)
    struct {
        ulonglong2 H[5][540];             // [u][swizzled col] packed {reI,imI,reO,imO} as 2x f32x2 pairs (see use)
    } stft;
    struct {
        float2 sxy[42][45];               // (x,y) pixel pairs, conflict-free pitch
        float2 hA[42][33];                // (hx, hy)
        float2 hB[42][33];                // (h_{xx+yy}, h_xy)
    } ssim;
};

__global__ void __launch_bounds__(256, 4) fused_kernel(const float* __restrict__ xin,
                                                       const float* __restrict__ xout)
{
    __shared__ SmemU S;
    const int tid = threadIdx.x;
    const int bid = blockIdx.x;

    if (bid < STFT_BLOCKS) {
        // =================== STFT path (R2 logic, 256 threads) ===================
        const int b = bid / 38;
        const int prow = bid - b * 38;    // image rows prow*4 .. prow*4+11

        const float* pin  = xin  + ((long)b * 160 + (long)prow * 4) * 480;
        const float* pout = xout + ((long)b * 160 + (long)prow * 4) * 480;

        // Phase A: column DFTs straight from gmem (coalesced across lanes)
        for (int e = tid; e < 480; e += 256) {
            float vi[12], vo[12];
            #pragma unroll
            for (int y = 0; y < 12; y++) {
                vi[y] = pin [y*480 + e];
                vo[y] = pout[y*480 + e];
            }
            float hir[5], hii[5], hor[5], hoi[5];
            dft12_5(vi, hir, hii);
            dft12_5(vo, hor, hoi);
            const int es = e + (e >> 3);  // bank swizzle
            #pragma unroll
            for (int u = 0; u < 5; u++) {
                float4 f = make_float4(hir[u], hii[u], hor[u], hoi[u]);
                S.stft.H[u][es] = *reinterpret_cast<ulonglong2*>(&f);
            }
        }
        __syncthreads();

        // Phase B: 570 items = 38 patches x 3 ch x 5 u
        float acc = 0.f;
        for (int id = tid; id < 570; id += 256) {
            const int u = id / 114;       // 0..4  (bin u+1)
            const int m = id - u*114;     // 0..113 = j*3 + c
            const int cch = m % 3;
            const int ebase = 4*m - 3*cch;  // = 12j + c

            float Fir[5], Fii[5], For[5], Foi[5];
            #pragma unroll
            for (int v = 0; v < 5; v++) { Fir[v]=0.f; Fii[v]=0.f; For[v]=0.f; Foi[v]=0.f; }

            #pragma unroll
            for (int x = 0; x < 12; x++) {
                const int e = ebase + 3*x;
                const int es = e + (e >> 3);
                ulonglong2 hraw = S.stft.H[u][es];
                float4 h = *reinterpret_cast<float4*>(&hraw);
                #pragma unroll
                for (int v = 1; v <= 5; v++) {
                    const int k = (v*x) % 12;
                    const float c_ = cw12f(k), s_ = sw12f(k);
                    const int vi = v - 1;
                    if (s_ == 0.f) {
                        if (c_ > 0.f) { Fir[vi]+=h.x; Fii[vi]+=h.y; For[vi]+=h.z; Foi[vi]+=h.w; }
                        else          { Fir[vi]-=h.x; Fii[vi]-=h.y; For[vi]-=h.z; Foi[vi]-=h.w; }
                    } else if (c_ == 0.f) {
                        if (s_ > 0.f) { Fir[vi]+=h.y; Fii[vi]-=h.x; For[vi]+=h.w; Foi[vi]-=h.z; }
                        else          { Fir[vi]-=h.y; Fii[vi]+=h.x; For[vi]-=h.w; Foi[vi]+=h.z; }
                    } else {
                        Fir[vi] = fmaf(h.x,  c_, fmaf(h.y,  s_, Fir[vi]));
                        Fii[vi] = fmaf(h.y,  c_, fmaf(h.x, -s_, Fii[vi]));
                        For[vi] = fmaf(h.z,  c_, fmaf(h.w,  s_, For[vi]));
                        Foi[vi] = fmaf(h.w,  c_, fmaf(h.z, -s_, Foi[vi]));
                    }
                }
            }

            const float wu = (float)(u + 1) * (1.f / 25.f);
            #pragma unroll
            for (int v = 1; v <= 5; v++) {
                const int vi = v - 1;
                float angi = fast_atan2f(Fii[vi], Fir[vi] + 1e-8f);
                float ango = fast_atan2f(Foi[vi], For[vi] + 1e-8f);
                float m2i = fmaf(Fir[vi], Fir[vi], Fii[vi]*Fii[vi]);
                float m2o = fmaf(For[vi], For[vi], Foi[vi]*Foi[vi]);
                float magi = m2i * __frsqrt_rn(fmaxf(m2i, 1e-30f));
                float mago = m2o * __frsqrt_rn(fmaxf(m2o, 1e-30f));
                acc = fmaf((float)v * wu, fabsf(ango - angi) + fabsf(mago - magi), acc);
            }
        }

        __syncthreads();                  // red aliases H: all reads must finish
        S.red[tid] = acc;
        __syncthreads();
        #pragma unroll
        for (int s = 128; s > 0; s >>= 1) {
            if (tid < s) S.red[tid] += S.red[tid + s];
            __syncthreads();
        }
        if (tid == 0)
            g_stft[bid] = S.red[0];

    } else {
        // =================== SSIM path: 4 moment fields, k-outer both passes ===================
        const int idx = bid - STFT_BLOCKS;
        const int bz = idx / 25;          // b*3 + c
        const int r25 = idx - bz*25;
        const int by = r25 / 5, bx = r25 - by*5;
        const int c  = bz % 3, b = bz / 3;
        const int ox = bx * 32, oy = by * 32;

        const float* pin  = xin  + (size_t)b * (160*160*3) + c;
        const float* pout = xout + (size_t)b * (160*160*3) + c;

        // load 42x42 input tile (halo), zero-pad OOB (those outputs masked)
        for (int i = tid; i < 42*42; i += 256) {
            int r = i / 42, cc = i - r*42;
            int gr = oy + r, gc = ox + cc;
            float vx = 0.f, vy = 0.f;
            if (gr < 160 && gc < 160) {
                size_t off = ((size_t)gr*160 + gc) * 3;
                vx = pin[off]; vy = pout[off];
            }
            S.ssim.sxy[r][cc] = make_float2(vx, vy);
        }
        __syncthreads();

        // horizontal pass: 42 rows x 8 groups of 4 cols, k-outer (each pixel read once/group)
        for (int i = tid; i < 42*8; i += 256) {
            int r = i >> 3, c0 = (i & 7) * 4;
            float2 A[4], Bv[4];
            #pragma unroll
            for (int g = 0; g < 4; g++) { A[g] = make_float2(0.f,0.f); Bv[g] = make_float2(0.f,0.f); }
            #pragma unroll
            for (int k = 0; k < 14; k++) {
                float2 xy = S.ssim.sxy[r][c0 + k];
                float ss = fmaf(xy.y, xy.y, xy.x*xy.x);
                float ad = xy.x * xy.y;
                #pragma unroll
                for (int g = 0; g < 4; g++) {
                    const int kk = k - g;
                    if (kk >= 0 && kk < 11) {
                        const float w = GNW(kk);
                        A[g].x  = fmaf(w, xy.x, A[g].x);
                        A[g].y  = fmaf(w, xy.y, A[g].y);
                        Bv[g].x = fmaf(w, ss,   Bv[g].x);
                        Bv[g].y = fmaf(w, ad,   Bv[g].y);
                    }
                }
            }
            #pragma unroll
            for (int g = 0; g < 4; g++) {
                S.ssim.hA[r][c0 + g] = A[g];
                S.ssim.hB[r][c0 + g] = Bv[g];
            }
        }
        __syncthreads();

        // vertical pass: 32 cols x 8 row-groups, 4 outputs/thread, k-outer
        const int tx = tid & 31, ty = tid >> 5;
        const int rb = ty * 4;

        float2 aA[4], aB[4];
        #pragma unroll
        for (int g = 0; g < 4; g++) { aA[g] = make_float2(0.f,0.f); aB[g] = make_float2(0.f,0.f); }

        #pragma unroll
        for (int k = 0; k < 14; k++) {
            float2 tA = S.ssim.hA[rb + k][tx];
            float2 tB = S.ssim.hB[rb + k][tx];
            #pragma unroll
            for (int g = 0; g < 4; g++) {
                const int kk = k - g;
                if (kk >= 0 && kk < 11) {
                    const float w = GNW(kk);
                    aA[g].x = fmaf(w, tA.x, aA[g].x);
                    aA[g].y = fmaf(w, tA.y, aA[g].y);
                    aB[g].x = fmaf(w, tB.x, aB[g].x);
                    aB[g].y = fmaf(w, tB.y, aB[g].y);
                }
            }
        }

        float val = 0.f;
        const int gx = ox + tx;
        #pragma unroll
        for (int g = 0; g < 4; g++) {
            int gy = oy + rb + g;
            if (gx < 150 && gy < 150) {
                const float C1 = 1e-4f, C2 = 9e-4f;
                float mx = aA[g].x, my = aA[g].y;
                float vsum = aB[g].x - mx*mx - my*my;   // var_x + var_y
                float cov  = aB[g].y - mx*my;
                float lum = __fdividef(2.f*mx*my + C1, mx*mx + my*my + C1);
                float cs  = __fdividef(2.f*cov + C2, vsum + C2);
                val = fmaf(lum, cs, val);
            }
        }

        // red aliases sxy (only read in horizontal pass, already synced past)
        S.red[tid] = val;
        __syncthreads();
        #pragma unroll
        for (int s = 128; s > 0; s >>= 1) {
            if (tid < s) S.red[tid] += S.red[tid + s];
            __syncthreads();
        }
        if (tid == 0)
            g_ssim[idx] = S.red[0];
    }
}

// ---------------------------------------------------------------------------
// Final kernel: deterministic fixed-order fp64 reduction.
// loss = mean_b( -0.5*sum(1+lv-e^lv-m^2) + ssim_mean + 1e-4*stft_sum )
// ---------------------------------------------------------------------------
__global__ void __launch_bounds__(512) final_kernel(const float* __restrict__ mean,
                                                    const float* __restrict__ logvar,
                                                    float* __restrict__ out)
{
    __shared__ double red[512];
    const int tid = threadIdx.x;
    double acc = 0.0;

    const double K_KLD  = -0.5 / 32.0;
    const double K_SSIM = 1.0 / (32.0 * 150.0 * 150.0 * 3.0);
    const double K_STFT = 1e-4 / 32.0;

    for (int i = tid; i < 32*128; i += 512) {
        float lv = logvar[i], m = mean[i];
        acc += (double)(1.0f + lv - expf(lv) - m*m) * K_KLD;
    }
    for (int i = tid; i < SSIM_BLOCKS; i += 512)
        acc += (double)g_ssim[i] * K_SSIM;
    for (int i = tid; i < STFT_BLOCKS; i += 512)
        acc += (double)g_stft[i] * K_STFT;

    red[tid] = acc;
    __syncthreads();
    #pragma unroll
    for (int s = 256; s > 0; s >>= 1) {
        if (tid < s) red[tid] += red[tid + s];
        __syncthreads();
    }
    if (tid == 0) out[0] = (float)red[0];
}

// ---------------------------------------------------------------------------
extern "C" void kernel_launch(void* const* d_in, const int* in_sizes, int n_in,
                              void* d_out, int out_size)
{
    const float* mean   = (const float*)d_in[0];
    const float* logvar = (const float*)d_in[1];
    const float* xin    = (const float*)d_in[2];
    const float* xout   = (const float*)d_in[3];
    float* out = (float*)d_out;

    fused_kernel<<<TOTAL_BLOCKS, 256>>>(xin, xout);
    final_kernel<<<1, 512>>>(mean, logvar, out);
}